// round 3
// baseline (speedup 1.0000x reference)
#include <cuda_runtime.h>
#include <math.h>

#define N_NODES 50000
#define N_EDGES 800000
#define NFEAT   256
#define NHID    64
#define NCLASS  40
#define LOGSM_OFF (N_NODES * NCLASS)

typedef unsigned long long ull;

// ---------------------------------------------------------------------------
// Scratch (static __device__ — no allocations allowed)
// ---------------------------------------------------------------------------
__device__ float g_A[N_NODES * NHID];      // x @ W1
__device__ float g_h[N_NODES * NHID];      // spmm1 result
__device__ float g_B[N_NODES * NCLASS];    // relu(h+b1) @ W2
__device__ float g_l[N_NODES * NCLASS];    // spmm2 result

// CSR scratch
__device__ int   g_deg[N_NODES];
__device__ int   g_cnt[N_NODES];
__device__ int   g_off[N_NODES + 1];
__device__ int   g_src_csr[N_EDGES];
__device__ float g_w_csr[N_EDGES];

// ---------------------------------------------------------------------------
// f32x2 packed-FMA helpers (2x fp32 rate on sm_103a, PTX-only path)
// ---------------------------------------------------------------------------
__device__ __forceinline__ void ffma2(ull& acc, ull ab, ull w) {
    asm("fma.rn.f32x2 %0, %1, %2, %0;" : "+l"(acc) : "l"(ab), "l"(w));
}
__device__ __forceinline__ ull pack2(float v) {
    ull r;
    asm("mov.b64 %0, {%1, %1};" : "=l"(r) : "r"(__float_as_uint(v)));
    return r;
}
union F4U2 { float4 f4; ull u2[2]; };

// ---------------------------------------------------------------------------
// CSR build
// ---------------------------------------------------------------------------
__global__ void zero_counters_kernel() {
    int i = blockIdx.x * blockDim.x + threadIdx.x;
    if (i < N_NODES) { g_deg[i] = 0; g_cnt[i] = 0; }
}

__global__ void hist_kernel(const int* __restrict__ edst) {
    int e = blockIdx.x * blockDim.x + threadIdx.x;
    if (e < N_EDGES) atomicAdd(&g_deg[edst[e]], 1);
}

__global__ __launch_bounds__(1024) void scan_kernel() {
    __shared__ int part[1024];
    const int ITEMS = (N_NODES + 1023) / 1024; // 49
    int t = threadIdx.x;
    int base = t * ITEMS;

    int s = 0;
    for (int i = 0; i < ITEMS; i++) {
        int idx = base + i;
        if (idx < N_NODES) s += g_deg[idx];
    }
    part[t] = s;
    __syncthreads();
    // Hillis-Steele inclusive scan over 1024 partials
    for (int off = 1; off < 1024; off <<= 1) {
        int add = (t >= off) ? part[t - off] : 0;
        __syncthreads();
        part[t] += add;
        __syncthreads();
    }
    int excl = part[t] - s;
    for (int i = 0; i < ITEMS; i++) {
        int idx = base + i;
        if (idx < N_NODES) {
            g_off[idx] = excl;
            excl += g_deg[idx];
        }
    }
    if (t == 1023) g_off[N_NODES] = part[1023];
}

__global__ void scatter_kernel(const float* __restrict__ ew,
                               const int* __restrict__ esrc,
                               const int* __restrict__ edst) {
    int e = blockIdx.x * blockDim.x + threadIdx.x;
    if (e >= N_EDGES) return;
    int d = edst[e];
    int pos = g_off[d] + atomicAdd(&g_cnt[d], 1);
    g_src_csr[pos] = esrc[e];
    g_w_csr[pos]   = ew[e];
}

// ---------------------------------------------------------------------------
// GEMM1: g_A = x @ W1   (f32x2 packed FMA; W1 staged in smem, 2 phases)
// ---------------------------------------------------------------------------
__global__ __launch_bounds__(128) void gemm1_kernel(const float* __restrict__ x,
                                                    const float* __restrict__ W1) {
    __shared__ float W1s[128 * NHID]; // 32 KB

    int node = blockIdx.x * 128 + threadIdx.x;
    bool valid = (node < N_NODES);
    int n0 = valid ? node : 0;

    ull acc[32];
#pragma unroll
    for (int j = 0; j < 32; j++) acc[j] = 0ull; // {0.f,0.f}

    const float4* xv = (const float4*)x;

    for (int ph = 0; ph < 2; ph++) {
        __syncthreads();
        {
            const float4* Wg = (const float4*)(W1 + ph * 128 * NHID);
            float4* Ws = (float4*)W1s;
            for (int i = threadIdx.x; i < (128 * NHID) / 4; i += 128)
                Ws[i] = Wg[i];
        }
        __syncthreads();

        int kbase = ph * 128;
#pragma unroll 2
        for (int kk = 0; kk < 128; kk += 4) {
            float4 xa = xv[n0 * (NFEAT / 4) + (kbase + kk) / 4];
            float xs[4] = {xa.x, xa.y, xa.z, xa.w};
#pragma unroll
            for (int u = 0; u < 4; u++) {
                ull vv = pack2(xs[u]);
                const float4* wrow = (const float4*)(W1s + (kk + u) * NHID);
#pragma unroll
                for (int jj = 0; jj < 16; jj++) {
                    F4U2 w; w.f4 = wrow[jj];
                    ffma2(acc[2 * jj],     vv, w.u2[0]);
                    ffma2(acc[2 * jj + 1], vv, w.u2[1]);
                }
            }
        }
    }

    if (valid) {
        float4* out = (float4*)g_A;
#pragma unroll
        for (int jj = 0; jj < 16; jj++) {
            F4U2 o; o.u2[0] = acc[2 * jj]; o.u2[1] = acc[2 * jj + 1];
            out[n0 * 16 + jj] = o.f4;
        }
    }
}

// ---------------------------------------------------------------------------
// SpMM1 gather: g_h[n] = sum_{e in CSR[n]} g_A[src(e)] * w(e)
// 16 threads per node, one float4 column-chunk each. No atomics.
// ---------------------------------------------------------------------------
__global__ void spmm1_gather_kernel() {
    int gid = blockIdx.x * blockDim.x + threadIdx.x;
    int node = gid >> 4;
    if (node >= N_NODES) return;
    int q = gid & 15;

    int p   = g_off[node];
    int end = g_off[node + 1];

    const float4* A = (const float4*)g_A;
    float4 acc0 = make_float4(0.f, 0.f, 0.f, 0.f);
    float4 acc1 = make_float4(0.f, 0.f, 0.f, 0.f);

    for (; p + 1 < end; p += 2) {
        int   s0 = g_src_csr[p],     s1 = g_src_csr[p + 1];
        float w0 = g_w_csr[p],       w1 = g_w_csr[p + 1];
        float4 a0 = A[s0 * 16 + q];
        float4 a1 = A[s1 * 16 + q];
        acc0.x += a0.x * w0; acc0.y += a0.y * w0; acc0.z += a0.z * w0; acc0.w += a0.w * w0;
        acc1.x += a1.x * w1; acc1.y += a1.y * w1; acc1.z += a1.z * w1; acc1.w += a1.w * w1;
    }
    if (p < end) {
        int s0 = g_src_csr[p]; float w0 = g_w_csr[p];
        float4 a0 = A[s0 * 16 + q];
        acc0.x += a0.x * w0; acc0.y += a0.y * w0; acc0.z += a0.z * w0; acc0.w += a0.w * w0;
    }
    acc0.x += acc1.x; acc0.y += acc1.y; acc0.z += acc1.z; acc0.w += acc1.w;
    ((float4*)g_h)[node * 16 + q] = acc0;
}

// ---------------------------------------------------------------------------
// Layer2: h = relu(g_h + b1); g_B = h @ W2  (f32x2; 2 threads/node, 20 cols)
// ---------------------------------------------------------------------------
__global__ __launch_bounds__(256) void layer2_kernel(const float* __restrict__ b1,
                                                     const float* __restrict__ W2) {
    __shared__ float W2s[NHID * NCLASS]; // 10 KB
    __shared__ float b1s[NHID];

    for (int i = threadIdx.x; i < NHID * NCLASS; i += 256) W2s[i] = W2[i];
    if (threadIdx.x < NHID) b1s[threadIdx.x] = b1[threadIdx.x];
    __syncthreads();

    int tid = blockIdx.x * 256 + threadIdx.x;
    int node = tid >> 1;
    int half = tid & 1;
    if (node >= N_NODES) return;
    int cbase = half * 20;

    ull acc[10];
#pragma unroll
    for (int j = 0; j < 10; j++) acc[j] = 0ull;

    const float4* hin = (const float4*)(g_h + node * NHID);
#pragma unroll 4
    for (int k4 = 0; k4 < 16; k4++) {
        float4 hv = hin[k4];
        float hs[4] = {hv.x, hv.y, hv.z, hv.w};
#pragma unroll
        for (int u = 0; u < 4; u++) {
            int k = k4 * 4 + u;
            float h = fmaxf(hs[u] + b1s[k], 0.f);
            ull hh = pack2(h);
            const float4* wrow = (const float4*)(W2s + k * NCLASS + cbase);
#pragma unroll
            for (int jj = 0; jj < 5; jj++) {
                F4U2 w; w.f4 = wrow[jj];
                ffma2(acc[2 * jj],     hh, w.u2[0]);
                ffma2(acc[2 * jj + 1], hh, w.u2[1]);
            }
        }
    }

    float4* out = (float4*)(g_B + node * NCLASS + cbase);
#pragma unroll
    for (int jj = 0; jj < 5; jj++) {
        F4U2 o; o.u2[0] = acc[2 * jj]; o.u2[1] = acc[2 * jj + 1];
        out[jj] = o.f4;
    }
}

// ---------------------------------------------------------------------------
// SpMM2 gather: g_l[n] = sum g_B[src] * w  (16 threads/node, 10 active)
// ---------------------------------------------------------------------------
__global__ void spmm2_gather_kernel() {
    int gid = blockIdx.x * blockDim.x + threadIdx.x;
    int node = gid >> 4;
    if (node >= N_NODES) return;
    int q = gid & 15;
    if (q >= 10) return;

    int p   = g_off[node];
    int end = g_off[node + 1];

    const float4* B = (const float4*)g_B;
    float4 acc0 = make_float4(0.f, 0.f, 0.f, 0.f);
    float4 acc1 = make_float4(0.f, 0.f, 0.f, 0.f);

    for (; p + 1 < end; p += 2) {
        int   s0 = g_src_csr[p],     s1 = g_src_csr[p + 1];
        float w0 = g_w_csr[p],       w1 = g_w_csr[p + 1];
        float4 a0 = B[s0 * 10 + q];
        float4 a1 = B[s1 * 10 + q];
        acc0.x += a0.x * w0; acc0.y += a0.y * w0; acc0.z += a0.z * w0; acc0.w += a0.w * w0;
        acc1.x += a1.x * w1; acc1.y += a1.y * w1; acc1.z += a1.z * w1; acc1.w += a1.w * w1;
    }
    if (p < end) {
        int s0 = g_src_csr[p]; float w0 = g_w_csr[p];
        float4 a0 = B[s0 * 10 + q];
        acc0.x += a0.x * w0; acc0.y += a0.y * w0; acc0.z += a0.z * w0; acc0.w += a0.w * w0;
    }
    acc0.x += acc1.x; acc0.y += acc1.y; acc0.z += acc1.z; acc0.w += acc1.w;
    ((float4*)g_l)[node * 10 + q] = acc0;
}

// ---------------------------------------------------------------------------
// Finalize: logits = g_l + b2; out[0:2M]=logits, out[2M:4M]=log_softmax
// ---------------------------------------------------------------------------
__global__ __launch_bounds__(128) void finalize_kernel(const float* __restrict__ b2,
                                                       float* __restrict__ out) {
    __shared__ float b2s[NCLASS];
    if (threadIdx.x < NCLASS) b2s[threadIdx.x] = b2[threadIdx.x];
    __syncthreads();

    int node = blockIdx.x * 128 + threadIdx.x;
    if (node >= N_NODES) return;

    float v[NCLASS];
    float mx = -INFINITY;
    const float4* lin = (const float4*)(g_l + node * NCLASS);
#pragma unroll
    for (int jj = 0; jj < 10; jj++) {
        float4 a = lin[jj];
        v[jj * 4 + 0] = a.x + b2s[jj * 4 + 0];
        v[jj * 4 + 1] = a.y + b2s[jj * 4 + 1];
        v[jj * 4 + 2] = a.z + b2s[jj * 4 + 2];
        v[jj * 4 + 3] = a.w + b2s[jj * 4 + 3];
    }
#pragma unroll
    for (int j = 0; j < NCLASS; j++) mx = fmaxf(mx, v[j]);
    float s = 0.f;
#pragma unroll
    for (int j = 0; j < NCLASS; j++) s += expf(v[j] - mx);
    float lse = mx + logf(s);

    float4* o1 = (float4*)(out + node * NCLASS);
    float4* o2 = (float4*)(out + LOGSM_OFF + node * NCLASS);
#pragma unroll
    for (int jj = 0; jj < 10; jj++) {
        float4 a = make_float4(v[jj * 4 + 0], v[jj * 4 + 1],
                               v[jj * 4 + 2], v[jj * 4 + 3]);
        o1[jj] = a;
        float4 b = make_float4(a.x - lse, a.y - lse, a.z - lse, a.w - lse);
        o2[jj] = b;
    }
}

// ---------------------------------------------------------------------------
extern "C" void kernel_launch(void* const* d_in, const int* in_sizes, int n_in,
                              void* d_out, int out_size) {
    const float* x   = (const float*)d_in[0];
    const float* W1  = (const float*)d_in[1];
    const float* b1  = (const float*)d_in[2];
    const float* W2  = (const float*)d_in[3];
    const float* b2  = (const float*)d_in[4];
    const float* ew  = (const float*)d_in[5];
    const int*  esrc = (const int*)d_in[6];
    const int*  edst = (const int*)d_in[7];
    float* out = (float*)d_out;

    // CSR build (every call — graph replays must redo all work)
    zero_counters_kernel<<<(N_NODES + 255) / 256, 256>>>();
    hist_kernel<<<(N_EDGES + 255) / 256, 256>>>(edst);
    scan_kernel<<<1, 1024>>>();
    scatter_kernel<<<(N_EDGES + 255) / 256, 256>>>(ew, esrc, edst);

    // GEMM1 (can overlap CSR build in issue order; same stream = serial, fine)
    gemm1_kernel<<<(N_NODES + 127) / 128, 128>>>(x, W1);

    // SpMM1 gather
    {
        int total = N_NODES * 16;
        spmm1_gather_kernel<<<(total + 255) / 256, 256>>>();
    }
    // ReLU + bias + GEMM2
    {
        int total = N_NODES * 2;
        layer2_kernel<<<(total + 255) / 256, 256>>>(b1, W2);
    }
    // SpMM2 gather
    {
        int total = N_NODES * 16;
        spmm2_gather_kernel<<<(total + 255) / 256, 256>>>();
    }
    // bias + log_softmax + write both outputs
    finalize_kernel<<<(N_NODES + 127) / 128, 128>>>(b2, out);
}

// round 4
// speedup vs baseline: 1.1995x; 1.1995x over previous
#include <cuda_runtime.h>
#include <math.h>

#define N_NODES 50000
#define N_EDGES 800000
#define NFEAT   256
#define NHID    64
#define NCLASS  40
#define LOGSM_OFF (N_NODES * NCLASS)

typedef unsigned long long ull;

// Scratch (static __device__ — no allocations allowed)
__device__ float g_A[N_NODES * NHID];      // x @ W1
__device__ float g_hacc[N_NODES * NHID];   // spmm1 accumulator
__device__ float g_B[N_NODES * NCLASS];    // relu(hacc+b1) @ W2
__device__ float g_lacc[N_NODES * NCLASS]; // spmm2 accumulator

// ---------------------------------------------------------------------------
// f32x2 packed-FMA helpers (2x fp32 rate on sm_103a, PTX-only path)
// ---------------------------------------------------------------------------
__device__ __forceinline__ void ffma2(ull& acc, ull ab, ull w) {
    asm("fma.rn.f32x2 %0, %1, %2, %0;" : "+l"(acc) : "l"(ab), "l"(w));
}
__device__ __forceinline__ ull pack2(float v) {
    ull r;
    asm("mov.b64 %0, {%1, %1};" : "=l"(r) : "r"(__float_as_uint(v)));
    return r;
}
union F4U2 { float4 f4; ull u2[2]; };

// ---------------------------------------------------------------------------
// Zero both accumulators (must run every launch — graph replays reuse state)
// ---------------------------------------------------------------------------
__global__ void zero_acc_kernel() {
    int i = blockIdx.x * blockDim.x + threadIdx.x;
    float4 z = make_float4(0.f, 0.f, 0.f, 0.f);
    if (i < (N_NODES * NHID) / 4)   ((float4*)g_hacc)[i] = z;
    if (i < (N_NODES * NCLASS) / 4) ((float4*)g_lacc)[i] = z;
}

// ---------------------------------------------------------------------------
// GEMM1: g_A = x @ W1   [50000,256]@[256,64]  (f32x2; W1 smem, 2 phases)
// ---------------------------------------------------------------------------
__global__ __launch_bounds__(128) void gemm1_kernel(const float* __restrict__ x,
                                                    const float* __restrict__ W1) {
    __shared__ float W1s[128 * NHID]; // 32 KB

    int node = blockIdx.x * 128 + threadIdx.x;
    bool valid = (node < N_NODES);
    int n0 = valid ? node : 0;

    ull acc[32];
#pragma unroll
    for (int j = 0; j < 32; j++) acc[j] = 0ull;

    const float4* xv = (const float4*)x;

    for (int ph = 0; ph < 2; ph++) {
        __syncthreads();
        {
            const float4* Wg = (const float4*)(W1 + ph * 128 * NHID);
            float4* Ws = (float4*)W1s;
            for (int i = threadIdx.x; i < (128 * NHID) / 4; i += 128)
                Ws[i] = Wg[i];
        }
        __syncthreads();

        int kbase = ph * 128;
#pragma unroll 2
        for (int kk = 0; kk < 128; kk += 4) {
            float4 xa = xv[n0 * (NFEAT / 4) + (kbase + kk) / 4];
            float xs[4] = {xa.x, xa.y, xa.z, xa.w};
#pragma unroll
            for (int u = 0; u < 4; u++) {
                ull vv = pack2(xs[u]);
                const float4* wrow = (const float4*)(W1s + (kk + u) * NHID);
#pragma unroll
                for (int jj = 0; jj < 16; jj++) {
                    F4U2 w; w.f4 = wrow[jj];
                    ffma2(acc[2 * jj],     vv, w.u2[0]);
                    ffma2(acc[2 * jj + 1], vv, w.u2[1]);
                }
            }
        }
    }

    if (valid) {
        float4* out = (float4*)g_A;
#pragma unroll
        for (int jj = 0; jj < 16; jj++) {
            F4U2 o; o.u2[0] = acc[2 * jj]; o.u2[1] = acc[2 * jj + 1];
            out[n0 * 16 + jj] = o.f4;
        }
    }
}

// ---------------------------------------------------------------------------
// SpMM1: g_hacc[dst] += g_A[src] * w   (16 threads/edge, ONE float4 RED each)
// ---------------------------------------------------------------------------
__global__ void spmm1_kernel(const float* __restrict__ ew,
                             const int* __restrict__ esrc,
                             const int* __restrict__ edst) {
    int gid = blockIdx.x * blockDim.x + threadIdx.x;
    int e = gid >> 4;
    if (e >= N_EDGES) return;
    int q = gid & 15;

    int s = __ldg(&esrc[e]);
    int d = __ldg(&edst[e]);
    float w = __ldg(&ew[e]);

    float4 a = ((const float4*)g_A)[s * 16 + q];
    float4 m = make_float4(a.x * w, a.y * w, a.z * w, a.w * w);
    atomicAdd((float4*)&g_hacc[d * NHID + q * 4], m);
}

// ---------------------------------------------------------------------------
// Layer2: h = relu(g_hacc + b1); g_B = h @ W2  (f32x2; 2 threads/node)
// ---------------------------------------------------------------------------
__global__ __launch_bounds__(256) void layer2_kernel(const float* __restrict__ b1,
                                                     const float* __restrict__ W2) {
    __shared__ float W2s[NHID * NCLASS]; // 10 KB
    __shared__ float b1s[NHID];

    for (int i = threadIdx.x; i < NHID * NCLASS; i += 256) W2s[i] = W2[i];
    if (threadIdx.x < NHID) b1s[threadIdx.x] = b1[threadIdx.x];
    __syncthreads();

    int tid = blockIdx.x * 256 + threadIdx.x;
    int node = tid >> 1;
    int half = tid & 1;
    if (node >= N_NODES) return;
    int cbase = half * 20;

    ull acc[10];
#pragma unroll
    for (int j = 0; j < 10; j++) acc[j] = 0ull;

    const float4* hin = (const float4*)(g_hacc + node * NHID);
#pragma unroll 4
    for (int k4 = 0; k4 < 16; k4++) {
        float4 hv = hin[k4];
        float hs[4] = {hv.x, hv.y, hv.z, hv.w};
#pragma unroll
        for (int u = 0; u < 4; u++) {
            int k = k4 * 4 + u;
            float h = fmaxf(hs[u] + b1s[k], 0.f);
            ull hh = pack2(h);
            const float4* wrow = (const float4*)(W2s + k * NCLASS + cbase);
#pragma unroll
            for (int jj = 0; jj < 5; jj++) {
                F4U2 w; w.f4 = wrow[jj];
                ffma2(acc[2 * jj],     hh, w.u2[0]);
                ffma2(acc[2 * jj + 1], hh, w.u2[1]);
            }
        }
    }

    float4* out = (float4*)(g_B + node * NCLASS + cbase);
#pragma unroll
    for (int jj = 0; jj < 5; jj++) {
        F4U2 o; o.u2[0] = acc[2 * jj]; o.u2[1] = acc[2 * jj + 1];
        out[jj] = o.f4;
    }
}

// ---------------------------------------------------------------------------
// SpMM2: g_lacc[dst] += g_B[src] * w   (10 threads/edge, ONE float4 RED each)
// ---------------------------------------------------------------------------
__global__ void spmm2_kernel(const float* __restrict__ ew,
                             const int* __restrict__ esrc,
                             const int* __restrict__ edst) {
    int gid = blockIdx.x * blockDim.x + threadIdx.x;
    int e = gid / 10;
    if (e >= N_EDGES) return;
    int q = gid - e * 10;

    int s = __ldg(&esrc[e]);
    int d = __ldg(&edst[e]);
    float w = __ldg(&ew[e]);

    float4 a = ((const float4*)g_B)[s * 10 + q];
    float4 m = make_float4(a.x * w, a.y * w, a.z * w, a.w * w);
    atomicAdd((float4*)&g_lacc[d * NCLASS + q * 4], m);
}

// ---------------------------------------------------------------------------
// Finalize: logits = g_lacc + b2; out[0:2M]=logits, out[2M:4M]=log_softmax
// ---------------------------------------------------------------------------
__global__ __launch_bounds__(128) void finalize_kernel(const float* __restrict__ b2,
                                                       float* __restrict__ out) {
    __shared__ float b2s[NCLASS];
    if (threadIdx.x < NCLASS) b2s[threadIdx.x] = b2[threadIdx.x];
    __syncthreads();

    int node = blockIdx.x * 128 + threadIdx.x;
    if (node >= N_NODES) return;

    float v[NCLASS];
    float mx = -INFINITY;
    const float4* lin = (const float4*)(g_lacc + node * NCLASS);
#pragma unroll
    for (int jj = 0; jj < 10; jj++) {
        float4 a = lin[jj];
        v[jj * 4 + 0] = a.x + b2s[jj * 4 + 0];
        v[jj * 4 + 1] = a.y + b2s[jj * 4 + 1];
        v[jj * 4 + 2] = a.z + b2s[jj * 4 + 2];
        v[jj * 4 + 3] = a.w + b2s[jj * 4 + 3];
    }
#pragma unroll
    for (int j = 0; j < NCLASS; j++) mx = fmaxf(mx, v[j]);
    float s = 0.f;
#pragma unroll
    for (int j = 0; j < NCLASS; j++) s += expf(v[j] - mx);
    float lse = mx + logf(s);

    float4* o1 = (float4*)(out + node * NCLASS);
    float4* o2 = (float4*)(out + LOGSM_OFF + node * NCLASS);
#pragma unroll
    for (int jj = 0; jj < 10; jj++) {
        float4 a = make_float4(v[jj * 4 + 0], v[jj * 4 + 1],
                               v[jj * 4 + 2], v[jj * 4 + 3]);
        o1[jj] = a;
        float4 b = make_float4(a.x - lse, a.y - lse, a.z - lse, a.w - lse);
        o2[jj] = b;
    }
}

// ---------------------------------------------------------------------------
extern "C" void kernel_launch(void* const* d_in, const int* in_sizes, int n_in,
                              void* d_out, int out_size) {
    const float* x   = (const float*)d_in[0];
    const float* W1  = (const float*)d_in[1];
    const float* b1  = (const float*)d_in[2];
    const float* W2  = (const float*)d_in[3];
    const float* b2  = (const float*)d_in[4];
    const float* ew  = (const float*)d_in[5];
    const int*  esrc = (const int*)d_in[6];
    const int*  edst = (const int*)d_in[7];
    float* out = (float*)d_out;

    // Zero accumulators (every call — graph replays)
    {
        int n4 = (N_NODES * NHID) / 4; // 800000 covers lacc's 500000 too
        zero_acc_kernel<<<(n4 + 255) / 256, 256>>>();
    }
    // GEMM1 (f32x2)
    gemm1_kernel<<<(N_NODES + 127) / 128, 128>>>(x, W1);
    // SpMM1 (vector RED scatter)
    {
        int total = N_EDGES * 16; // 12.8M
        spmm1_kernel<<<(total + 255) / 256, 256>>>(ew, esrc, edst);
    }
    // ReLU + bias + GEMM2 (f32x2)
    {
        int total = N_NODES * 2;
        layer2_kernel<<<(total + 255) / 256, 256>>>(b1, W2);
    }
    // SpMM2 (vector RED scatter)
    {
        int total = N_EDGES * 10; // 8M
        spmm2_kernel<<<(total + 255) / 256, 256>>>(ew, esrc, edst);
    }
    // bias + log_softmax + write both outputs
    finalize_kernel<<<(N_NODES + 127) / 128, 128>>>(b2, out);
}